// round 16
// baseline (speedup 1.0000x reference)
#include <cuda_runtime.h>
#include <cuda_bf16.h>

#define N_NODES 50000
#define N_EDGES 800000
#define D_IN    128
#define D_OUT   64

typedef unsigned long long ull;

// Scratch for h = x @ W (12.8 MB fp32; L2-resident during scatter)
__device__ float g_h[N_NODES * D_OUT];

// Packed fp32x2 FMA: d = a*b + d per 32-bit lane.
__device__ __forceinline__ void ffma2(ull& d, ull a, ull b) {
    asm("fma.rn.f32x2 %0, %1, %2, %0;" : "+l"(d) : "l"(a), "l"(b));
}

__device__ __forceinline__ ull dup32(float f) {
    const unsigned u = __float_as_uint(f);
    return ((ull)u << 32) | u;
}
__device__ __forceinline__ ull pack2(float lo, float hi) {
    return ((ull)__float_as_uint(hi) << 32) | __float_as_uint(lo);
}

// ---------------------------------------------------------------------------
// Kernel 1: h = x @ W  (+ out = bias broadcast, fused)  -- unchanged (R14)
// 64-row tiles, 256 threads. Pair-packed x, pre-duplicated W: inner loop is
// pure LDS.128 + FFMA2 (22 issues / 2 k-steps), one barrier total.
// ---------------------------------------------------------------------------
__global__ __launch_bounds__(256, 2) void gemm_kernel(
    const float* __restrict__ x,
    const float* __restrict__ w,
    const float* __restrict__ bias,
    float* __restrict__ h,
    float* __restrict__ out)
{
    __shared__ __align__(16) ull Xp[32][130];    // pairs (r, r+32), pad 2
    __shared__ __align__(16) ull W2T[16][514];   // [colgroup][k*4+j], pad 2

    const int t = threadIdx.x;
    const int row0 = blockIdx.x * 64;

    // --- Stage W duplicated: 2048 float4, 8 per thread ---
    {
        const float4* w4 = (const float4*)w;     // idx = k*16 + c4
        #pragma unroll
        for (int i = 0; i < 8; i++) {
            const int idx = t + i * 256;
            const int k = idx >> 4, c4 = idx & 15;
            const float4 v = w4[idx];
            ull* dst = &W2T[c4][k * 4];
            dst[0] = dup32(v.x); dst[1] = dup32(v.y);
            dst[2] = dup32(v.z); dst[3] = dup32(v.w);
        }
    }

    // --- Stage x pairs: 1024 (r32, kq) units, 4 per thread ---
    {
        const float4* x4 = (const float4*)x;     // row stride = 32 float4
        #pragma unroll
        for (int i = 0; i < 4; i++) {
            const int unit = t + i * 256;
            const int r32 = unit >> 5, kq = unit & 31;
            int ra = row0 + r32;      if (ra > N_NODES - 1) ra = N_NODES - 1;
            int rb = row0 + r32 + 32; if (rb > N_NODES - 1) rb = N_NODES - 1;
            const float4 va = x4[ra * 32 + kq];
            const float4 vb = x4[rb * 32 + kq];
            Xp[r32][kq * 4 + 0] = pack2(va.x, vb.x);
            Xp[r32][kq * 4 + 1] = pack2(va.y, vb.y);
            Xp[r32][kq * 4 + 2] = pack2(va.z, vb.z);
            Xp[r32][kq * 4 + 3] = pack2(va.w, vb.w);
        }
    }
    __syncthreads();

    const int rg = t >> 4;    // 0..15
    const int cg = t & 15;    // 0..15 -> cols cg*4..+3
    const ull* wt = &W2T[cg][0];

    ull acc[2][4] = {};       // [pair: rg / rg+16][col]; lo=row, hi=row+32

    #pragma unroll 8
    for (int k = 0; k < D_IN; k += 2) {
        const ulonglong2 xa = *(const ulonglong2*)&Xp[rg][k];        // k, k+1
        const ulonglong2 xb = *(const ulonglong2*)&Xp[rg + 16][k];
        const ulonglong2 w0 = *(const ulonglong2*)&wt[k * 4];        // k: c0,c1
        const ulonglong2 w1 = *(const ulonglong2*)&wt[k * 4 + 2];    // k: c2,c3
        const ulonglong2 w2 = *(const ulonglong2*)&wt[k * 4 + 4];    // k+1
        const ulonglong2 w3 = *(const ulonglong2*)&wt[k * 4 + 6];

        ffma2(acc[0][0], xa.x, w0.x); ffma2(acc[0][1], xa.x, w0.y);
        ffma2(acc[0][2], xa.x, w1.x); ffma2(acc[0][3], xa.x, w1.y);
        ffma2(acc[1][0], xb.x, w0.x); ffma2(acc[1][1], xb.x, w0.y);
        ffma2(acc[1][2], xb.x, w1.x); ffma2(acc[1][3], xb.x, w1.y);

        ffma2(acc[0][0], xa.y, w2.x); ffma2(acc[0][1], xa.y, w2.y);
        ffma2(acc[0][2], xa.y, w3.x); ffma2(acc[0][3], xa.y, w3.y);
        ffma2(acc[1][0], xb.y, w2.x); ffma2(acc[1][1], xb.y, w2.y);
        ffma2(acc[1][2], xb.y, w3.x); ffma2(acc[1][3], xb.y, w3.y);
    }

    // --- Epilogue: h rows + fused out = bias ---
    const float4 bias4 = ((const float4*)bias)[cg];
    #pragma unroll
    for (int pair = 0; pair < 2; pair++) {
        #pragma unroll
        for (int half = 0; half < 2; half++) {
            const int lrow = rg + pair * 16 + half * 32;
            const int grow = row0 + lrow;
            if (grow < N_NODES) {
                float4 v;
                const uint2 a0 = *(const uint2*)&acc[pair][0];
                const uint2 a1 = *(const uint2*)&acc[pair][1];
                const uint2 a2 = *(const uint2*)&acc[pair][2];
                const uint2 a3 = *(const uint2*)&acc[pair][3];
                v.x = __uint_as_float(half ? a0.y : a0.x);
                v.y = __uint_as_float(half ? a1.y : a1.x);
                v.z = __uint_as_float(half ? a2.y : a2.x);
                v.w = __uint_as_float(half ? a3.y : a3.x);
                *(float4*)&h[(size_t)grow * D_OUT + cg * 4]   = v;
                *(float4*)&out[(size_t)grow * D_OUT + cg * 4] = bias4;
            }
        }
    }
}

// ---------------------------------------------------------------------------
// Kernel 2: scatter-add v2.
// 256 threads = 16 subgroups x 16 lanes; lane owns a float4 of dims.
// EPB=1024 edges/block staged in smem; subgroup runs 64 edges.
// Sorted dst => runs are globally contiguous:
//   - first run of a chunk (may extend before lo)  -> atomicAdd
//   - final run of a chunk (may extend past hi)    -> atomicAdd
//   - INTERIOR runs are EXCLUSIVELY owned          -> plain STG of bias+acc
// Depth-2 software prefetch of h rows doubles the per-subgroup MLP.
// ---------------------------------------------------------------------------
#define EPB 1024

__device__ __forceinline__ void flush_atomic(float* out, int node, int lane, float4 a)
{
    float* p = &out[(size_t)node * D_OUT + lane * 4];
    atomicAdd(p + 0, a.x);
    atomicAdd(p + 1, a.y);
    atomicAdd(p + 2, a.z);
    atomicAdd(p + 3, a.w);
}

__global__ __launch_bounds__(256) void scatter_kernel(
    const int*   __restrict__ src,
    const int*   __restrict__ dst,
    const float* __restrict__ vals,
    const float* __restrict__ bias,
    const float* __restrict__ h,
    float*       __restrict__ out)
{
    __shared__ __align__(16) int   s_src[EPB];
    __shared__ __align__(16) int   s_dst[EPB];
    __shared__ __align__(16) float s_val[EPB];

    const int t = threadIdx.x;
    const int e0 = blockIdx.x * EPB;
    int n = N_EDGES - e0;
    if (n > EPB) n = EPB;

    // Stage edge data: 256 threads x 4 edges (e0 is 1024-aligned -> vec ok)
    {
        const int e = e0 + t * 4;
        if (e + 3 < N_EDGES) {
            *(int4*)  &s_src[t * 4] = *(const int4*)  &src[e];
            *(int4*)  &s_dst[t * 4] = *(const int4*)  &dst[e];
            *(float4*)&s_val[t * 4] = *(const float4*)&vals[e];
        } else {
            #pragma unroll
            for (int j = 0; j < 4; j++) {
                if (e + j < N_EDGES) {
                    s_src[t * 4 + j] = src[e + j];
                    s_dst[t * 4 + j] = dst[e + j];
                    s_val[t * 4 + j] = vals[e + j];
                }
            }
        }
    }
    __syncthreads();

    const int sg   = t >> 4;     // subgroup 0..15
    const int lane = t & 15;     // float4 at dims [4*lane, 4*lane+4)
    const int lo = sg * (EPB / 16);
    int hi = lo + (EPB / 16);
    if (hi > n) hi = n;
    if (lo >= hi) return;

    const float4 bias4 = ((const float4*)bias)[lane];

    // Prefetch edges lo, lo+1
    int    d0 = s_dst[lo];
    float  v0 = s_val[lo];
    float4 h0 = *(const float4*)&h[(size_t)s_src[lo] * D_OUT + lane * 4];
    int d1 = 0; float v1 = 0.f; float4 h1 = make_float4(0.f, 0.f, 0.f, 0.f);
    if (lo + 1 < hi) {
        d1 = s_dst[lo + 1];
        v1 = s_val[lo + 1];
        h1 = *(const float4*)&h[(size_t)s_src[lo + 1] * D_OUT + lane * 4];
    }

    int cur = d0;
    bool first = true;           // first run may extend before lo -> atomic
    float4 acc = make_float4(0.f, 0.f, 0.f, 0.f);

    for (int i = lo; i < hi; i++) {
        // Prefetch edge i+2 (depth-2 pipeline)
        int d2 = 0; float v2 = 0.f; float4 h2 = make_float4(0.f, 0.f, 0.f, 0.f);
        if (i + 2 < hi) {
            d2 = s_dst[i + 2];
            v2 = s_val[i + 2];
            h2 = *(const float4*)&h[(size_t)s_src[i + 2] * D_OUT + lane * 4];
        }

        if (d0 != cur) {          // run boundary at i (run ended inside chunk)
            if (first) {
                flush_atomic(out, cur, lane, acc);
                first = false;
            } else {
                // Interior run: exclusively owned -> plain vector store
                float4 r;
                r.x = bias4.x + acc.x; r.y = bias4.y + acc.y;
                r.z = bias4.z + acc.z; r.w = bias4.w + acc.w;
                *(float4*)&out[(size_t)cur * D_OUT + lane * 4] = r;
            }
            acc = make_float4(0.f, 0.f, 0.f, 0.f);
            cur = d0;
        }
        acc.x = fmaf(v0, h0.x, acc.x);
        acc.y = fmaf(v0, h0.y, acc.y);
        acc.z = fmaf(v0, h0.z, acc.z);
        acc.w = fmaf(v0, h0.w, acc.w);

        d0 = d1; v0 = v1; h0 = h1;
        d1 = d2; v1 = v2; h1 = h2;
    }
    // Final run may extend past hi -> atomic
    flush_atomic(out, cur, lane, acc);
}

// ---------------------------------------------------------------------------
// Launch.  Inputs: x, edge_src, edge_dst, edge_vals, weight, bias
// ---------------------------------------------------------------------------
extern "C" void kernel_launch(void* const* d_in, const int* in_sizes, int n_in,
                              void* d_out, int out_size)
{
    const float* x        = (const float*)d_in[0];
    const int*   edge_src = (const int*)  d_in[1];
    const int*   edge_dst = (const int*)  d_in[2];
    const float* edge_val = (const float*)d_in[3];
    const float* weight   = (const float*)d_in[4];
    const float* bias     = (const float*)d_in[5];
    float*       out      = (float*)d_out;

    float* h;
    cudaGetSymbolAddress((void**)&h, g_h);

    // GEMM + fused bias-init of out
    gemm_kernel<<<(N_NODES + 63) / 64, 256>>>(x, weight, bias, h, out);

    // Scatter: out[dst] += val * h[src] (exclusive interior runs use stores)
    scatter_kernel<<<(N_EDGES + EPB - 1) / EPB, 256>>>(
        edge_src, edge_dst, edge_val, bias, h, out);
}